// round 15
// baseline (speedup 1.0000x reference)
#include <cuda_runtime.h>
#include <math.h>

#define NB 8
#define NGT 100
#define NC 80
#define T_TOTAL 13343
#define NT 256              // threads per block
#define NSEG 10             // 2 boxes x 5 levels
#define MAXC2 256           // combined cells (analytic worst 2*123=246)
#define IPC 5               // 16-class items per cell
#define PADC 261            // psum row pitch (261%32=5 -> conflict-spread)

__device__ __forceinline__ float neg_term(float v) {
    float cp = fminf(fmaxf(v, 1e-6f), 1.0f - 1e-6f);
    return (0.75f * (cp * cp)) * (-__logf(1.0f - cp));
}

// ---------------------------------------------------------------------------
// One block per PAIR of (batch, gt-box) (pairs never cross batch: 100 is
// even). Combined cell list over 10 (box,level) segments; same lazy-s_neg
// 4-phase pipeline as the 12.9us kernel, amortizing per-CTA overhead 2x.
// ---------------------------------------------------------------------------
__global__ __launch_bounds__(NT) void level_select_kernel(
        const float* __restrict__ cls,
        const float4* __restrict__ regr4,
        const float* __restrict__ gt,
        float* __restrict__ out) {
    const int   fdim_[5] = {100, 50, 25, 13, 7};
    const int   ls_[5]   = {0, 10000, 12500, 13125, 13294};
    const float st_[5]   = {8.f, 16.f, 32.f, 64.f, 128.f};

    int bn0  = blockIdx.x * 2;             // first box of the pair
    int b    = bn0 / NGT;                  // shared batch
    int tid  = threadIdx.x;
    int lane = tid & 31;
    int wid  = tid >> 5;

    __shared__ float  sbox[10];            // 2 boxes x 5 floats
    __shared__ int    svalid[2];
    __shared__ int    srx1[NSEG], sry1[NSEG], srnx[NSEG], srcnt[NSEG];
    __shared__ int    spre[NSEG + 1];
    __shared__ int    stc[MAXC2];          // combined cell -> flat location t
    __shared__ float  psum[IPC * PADC];    // [item][cell] neg-focal partials
    __shared__ float  sval[MAXC2];         // per-cell total loss
    __shared__ double slvl[NSEG];

    if (tid < 10) sbox[tid] = gt[(size_t)bn0 * 5 + tid];
    __syncthreads();

    // rect math once per (box,level) segment; invalid box -> cnt 0
    if (tid < NSEG) {
        int   h = tid / 5, l = tid - h * 5;
        float b0 = sbox[h * 5 + 0], b1 = sbox[h * 5 + 1];
        float b2 = sbox[h * 5 + 2], b3 = sbox[h * 5 + 3];
        bool  valid = (fabsf(b0) + fabsf(b1) + fabsf(b2) + fabsf(b3)) > 0.0f;
        if (l == 0) svalid[h] = valid;
        if (valid) {
            float stride = st_[l];
            int   fw = fdim_[l];
            float pb0 = b0 / stride, pb1 = b1 / stride;
            float pb2 = b2 / stride, pb3 = b3 / stride;
            float cx = (pb0 + pb2) * 0.5f, cy = (pb1 + pb3) * 0.5f;
            float hw = ((pb2 - pb0) * 0.2f) * 0.5f;
            float hh = ((pb3 - pb1) * 0.2f) * 0.5f;
            int x1 = (int)fminf(fmaxf(floorf(cx - hw), 0.0f), (float)(fw - 1));
            int y1 = (int)fminf(fmaxf(floorf(cy - hh), 0.0f), (float)(fw - 1));
            int x2 = min(max((int)ceilf(cx + hw), x1 + 1), fw);
            int y2 = min(max((int)ceilf(cy + hh), y1 + 1), fw);
            srx1[tid] = x1; sry1[tid] = y1;
            srnx[tid] = x2 - x1;
            srcnt[tid] = (x2 - x1) * (y2 - y1);
        } else {
            srx1[tid] = 0; sry1[tid] = 0; srnx[tid] = 1; srcnt[tid] = 0;
        }
    }
    __syncthreads();

    if (tid == 0) {
        int acc = 0;
        #pragma unroll
        for (int k = 0; k < NSEG; k++) { spre[k] = acc; acc += srcnt[k]; }
        spre[NSEG] = acc;
    }
    __syncthreads();
    int total = spre[NSEG];

    const float*  clsb  = cls   + (size_t)b * T_TOTAL * NC;
    const float4* clsb4 = (const float4*)clsb;
    const float4* regb  = regr4 + (size_t)b * T_TOTAL;

    // ---- Phase 0: thread per combined cell; early cp[label]/regr loads ----
    int   myseg = 0, myx = 0, myy = 0;
    float cpl = 0.0f;
    float4 r  = make_float4(0.f, 0.f, 0.f, 0.f);
    if (tid < total) {
        #pragma unroll
        for (int k = 1; k < NSEG; k++) if (tid >= spre[k]) myseg = k;
        int h  = myseg / 5, l = myseg - h * 5;
        int c  = tid - spre[myseg];
        int nx = srnx[myseg];
        myx = srx1[myseg] + c % nx;
        myy = sry1[myseg] + c / nx;
        int t = ls_[l] + myy * fdim_[l] + myx;
        stc[tid] = t;
        int label = (int)sbox[h * 5 + 4];
        cpl = clsb[(size_t)t * NC + label];     // in flight across phase 1
        r   = regb[t];                          // in flight across phase 1
    }
    __syncthreads();

    // ---- Phase 1: (cell, 16-class item) grid; 4 indep LDG.128 per item ----
    int items = total * IPC;                    // <= 1230 -> <= 5 iterations
    for (int i = tid; i < items; i += NT) {
        int cell = i / IPC;
        int q    = i - cell * IPC;
        int t    = stc[cell];
        const float4* p = clsb4 + t * (NC / 4) + q * 4;
        float4 v0 = p[0], v1 = p[1], v2 = p[2], v3 = p[3];
        float s = ((neg_term(v0.x) + neg_term(v0.y)) + (neg_term(v0.z) + neg_term(v0.w)))
                + ((neg_term(v1.x) + neg_term(v1.y)) + (neg_term(v1.z) + neg_term(v1.w)))
                + ((neg_term(v2.x) + neg_term(v2.y)) + (neg_term(v2.z) + neg_term(v2.w)))
                + ((neg_term(v3.x) + neg_term(v3.y)) + (neg_term(v3.z) + neg_term(v3.w)));
        psum[q * PADC + cell] = s;
    }
    __syncthreads();

    // ---- Phase 2: thread per combined cell ----
    if (tid < total) {
        int h = myseg / 5, l = myseg - h * 5;
        float b0 = sbox[h * 5 + 0], b1 = sbox[h * 5 + 1];
        float b2 = sbox[h * 5 + 2], b3 = sbox[h * 5 + 3];

        float sneg = ((psum[0 * PADC + tid] + psum[1 * PADC + tid])
                   +  (psum[2 * PADC + tid] + psum[3 * PADC + tid]))
                   +   psum[4 * PADC + tid];

        float cp = fminf(fmaxf(cpl, 1e-6f), 1.0f - 1e-6f);
        float om = 1.0f - cp;
        float neg_lab = (0.75f * (cp * cp)) * (-logf(om));
        float pos_lab = (0.25f * (om * om)) * (-logf(cp));

        float stride = st_[l];
        float sx = ((float)myx + 0.5f) * stride;
        float sy = ((float)myy + 0.5f) * stride;
        float tl = (sx - b0) * 0.25f, tt = (sy - b1) * 0.25f;
        float tr = (b2 - sx) * 0.25f, tb = (b3 - sy) * 0.25f;
        float t_area = (tl + tr) * (tt + tb);
        float p_area = (r.x + r.z) * (r.y + r.w);
        float wi = fminf(r.x, tl) + fminf(r.z, tr);
        float hi = fminf(r.y, tt) + fminf(r.w, tb);
        float ai = wi * hi;
        float un = t_area + p_area - ai;
        float iou = -logf((ai + 1.0f) / (un + 1.0f));  // NaN propagates

        sval[tid] = (sneg - neg_lab + pos_lab) + iou;
    }
    __syncthreads();

    // ---- Phase 3: 10 segment reductions over 8 warps (f64, fixed order) ----
    for (int j = wid; j < NSEG; j += NT / 32) {
        int pre = spre[j];
        int cnt = srcnt[j];
        if (cnt > 0) {
            double s = 0.0;
            for (int i = lane; i < cnt; i += 32) s += (double)sval[pre + i];
            #pragma unroll
            for (int o = 16; o; o >>= 1) s += __shfl_down_sync(0xffffffffu, s, o);
            if (lane == 0) slvl[j] = s / (double)cnt;
        }
    }
    __syncthreads();

    // ---- outputs: thread h < 2 writes box bn0+h ----
    if (tid < 2) {
        if (!svalid[tid]) {
            out[bn0 + tid] = -1.0f;
        } else {
            // numpy/jax argmin fold: pick if v<best, or v NaN and best not.
            int    base = tid * 5;
            int    best = 0;
            double bv   = slvl[base];
            #pragma unroll
            for (int k = 1; k < 5; k++) {
                double v = slvl[base + k];
                if ((v < bv) || ((v != v) && (bv == bv))) { bv = v; best = k; }
            }
            out[bn0 + tid] = (float)best;
        }
    }
}

extern "C" void kernel_launch(void* const* d_in, const int* in_sizes, int n_in,
                              void* d_out, int out_size) {
    const float* cls  = (const float*)d_in[0];   // (8, 13343, 80) f32
    const float* regr = (const float*)d_in[1];   // (8, 13343, 4)  f32
    // d_in[2] = feature_shapes (compile-time constants, unused)
    const float* gt   = (const float*)d_in[3];   // (8, 100, 5)    f32
    float* out = (float*)d_out;                  // (8, 100)       f32

    level_select_kernel<<<NB * NGT / 2, NT>>>(cls, (const float4*)regr, gt, out);
}